// round 8
// baseline (speedup 1.0000x reference)
#include <cuda_runtime.h>

#define BB 4
#define CC 256
#define HH 256
#define WW 256
#define HWSZ (HH * WW)
#define NPIX (BB * HWSZ)
#define FULLMASK 0xFFFFFFFFu

#define NBLK 444
#define NTHR 256
#define NTH_TOT (NBLK * NTHR)          // 113664 threads
#define NWARP (NBLK * 8)               // 3552 warps
#define NTASK (3 * 9 * 4 * 256)        // 27648 warp-tasks
#define PROWS 274                      // 2 zero rows, 256 data, 16 zero rows
#define SP 264                         // plane row stride in floats (66 float4)
#define SP4 66
#define PLSZ (PROWS * SP)              // floats per (plane, b)
#define PLSZ4 (PLSZ / 4)               // 18084 float4
#define ZROW 258                       // guaranteed-zero plane row

// channel-independent planes (float4-aligned). Plane col = image col + 2.
// fv: +-1 if correct (sign = class) else 0.   iv: +-1/(cnt+1e-5) if mse-masked else 0.
__device__ float4 g_fvp4[BB * PLSZ4];
__device__ float4 g_ivp4[BB * PLSZ4];
__device__ unsigned char g_info[NPIX];
__device__ double g_loss[2];
__device__ int g_nsel[2], g_cal[2];
__device__ int g_bar_count = 0;
__device__ volatile int g_bar_gen = 0;

__device__ __forceinline__ void gridsync() {
    __syncthreads();
    if (threadIdx.x == 0) {
        __threadfence();
        int gen = g_bar_gen;
        if (atomicAdd(&g_bar_count, 1) == NBLK - 1) {
            g_bar_count = 0;
            __threadfence();
            g_bar_gen = gen + 1;
        } else {
            while (g_bar_gen == gen) { __nanosleep(64); }
        }
        __threadfence();
    }
    __syncthreads();
}

__global__ void __launch_bounds__(NTHR, 3) kernFused(
    const float* __restrict__ x, const float* __restrict__ clf,
    const int* __restrict__ gt, float* __restrict__ out) {
    __shared__ double sred[2][8];
    const int tid0 = blockIdx.x * NTHR + threadIdx.x;

    // ===== Phase 1a: zero planes + per-pixel info ==========================
    {
        const float4 z4 = make_float4(0.f, 0.f, 0.f, 0.f);
        for (int i = tid0; i < BB * PLSZ4; i += NTH_TOT) {
            g_fvp4[i] = z4;
            g_ivp4[i] = z4;
        }
    }
    for (int p = tid0; p < NPIX; p += NTH_TOT) {
        if (p == 0) {
            g_loss[0] = 0.0; g_loss[1] = 0.0;
            g_nsel[0] = 0; g_nsel[1] = 0;
            g_cal[0] = 0; g_cal[1] = 0;
        }
        int b = p >> 16;
        int hw = p & (HWSZ - 1);
        int h = hw >> 8;
        int w = hw & (WW - 1);
        int g = gt[p];
        float c0 = clf[(size_t)(b * 2) * HWSZ + hw];
        float c1 = clf[(size_t)(b * 2 + 1) * HWSZ + hw];
        int pred = (c1 > c0) ? 1 : 0;          // argmax ties -> index 0
        int correct = (pred == g) ? 1 : 0;
        int edge = (g == -1) ? 1 : 0;
        if (h < HH - 5) edge |= (gt[p + 5 * WW] != g) ? 1 : 0;
        if (w < WW - 5) edge |= (gt[p + 5] != g) ? 1 : 0;
        g_info[p] = (unsigned char)((g & 1) | (correct << 1) | (edge << 2));
    }
    gridsync();

    // ===== Phase 1b: ring counts -> fv/iv planes + counters =================
    for (int p = tid0; p < NPIX; p += NTH_TOT) {
        int b = p >> 16;
        int hw = p & (HWSZ - 1);
        int h = hw >> 8;
        int w = hw & (WW - 1);
        unsigned info = g_info[p];
        int g = info & 1;
        int correct = (info >> 1) & 1;
        int edge = (info >> 2) & 1;
        int cntCorr = 0, cntCls = 0;
#pragma unroll
        for (int dh = -2; dh <= 2; dh++) {
#pragma unroll
            for (int dw = -2; dw <= 2; dw++) {
                if (dh == 0 && dw == 0) continue;
                int hh = h + dh, wp = w + dw;
                if ((unsigned)hh < HH && (unsigned)wp < WW) {
                    unsigned qi = g_info[p + dh * WW + dw];
                    int same = ((int)(qi & 1) == g) ? 1 : 0;
                    cntCls += same;
                    cntCorr += same & (int)((qi >> 1) & 1);
                }
            }
        }
        int mse = correct & edge & (cntCorr >= 1 ? 1 : 0);
        int cal = edge & (cntCls >= 1 ? 1 : 0);

        float fv = correct ? (g ? 1.0f : -1.0f) : 0.0f;
        float inv = 1.0f / ((float)cntCorr + 1e-5f);
        float ivs = mse ? (g ? inv : -inv) : 0.0f;

        int pofs = (h + 2) * SP + (w + 2);
        ((float*)g_fvp4)[(size_t)b * PLSZ + pofs] = fv;
        ((float*)g_ivp4)[(size_t)b * PLSZ + pofs] = ivs;

        unsigned bm;
        bm = __ballot_sync(FULLMASK, mse && g == 0);
        if ((threadIdx.x & 31) == 0 && bm) atomicAdd(&g_nsel[0], __popc(bm));
        bm = __ballot_sync(FULLMASK, mse && g == 1);
        if ((threadIdx.x & 31) == 0 && bm) atomicAdd(&g_nsel[1], __popc(bm));
        bm = __ballot_sync(FULLMASK, cal && g == 0);
        if ((threadIdx.x & 31) == 0 && bm) atomicAdd(&g_cal[0], __popc(bm));
        bm = __ballot_sync(FULLMASK, cal && g == 1);
        if ((threadIdx.x & 31) == 0 && bm) atomicAdd(&g_cal[1], __popc(bm));
    }
    gridsync();

    // ===== Phase 2: separable 2-class box filter, 4 cols/lane ==============
    // Task = (wband, hband, b, ch): 30 output rows x (124|124|8) output cols.
    // Lane owns image cols cb..cb+3, cb = 124*wband - 2 + 4*lane. Vertical:
    // 5-slot ring of products pt = x*|fv|, ps = x*fv; running col sums u,v.
    // Horizontal: 8 shuffles/row serve 4 px; window sums by in-lane prefix.
    // Out-of-image handled by plane padding + clamped x (broadcast) + masks.
    const int lane = threadIdx.x & 31;
    const int wid = threadIdx.x >> 5;
    const int gwarp = blockIdx.x * 8 + wid;
    float acc0 = 0.f, acc1 = 0.f;

#pragma unroll 1
    for (int t = gwarp; t < NTASK; t += NWARP) {
        int wb = t % 3;
        int r1 = t / 3;
        int hb = r1 % 9;
        int r2 = r1 / 9;
        int b = r2 & 3;
        int ch = r2 >> 2;
        int h0 = hb * 30;
        int cb = wb * 124 - 2 + (lane << 2);
        bool lv = (cb <= 255);
        int e0 = min(max(cb, 0), 254);
        int e1 = min(cb + 2, 254);
        float mA = (lane == 0 && wb > 0) ? 0.f : 1.f;
        float mB = (lane == 31 && wb < 2) ? 0.f : 1.f;
        int pq = (cb + 2) >> 2;                 // float4 col in planes
        int f4s = lv ? SP4 : 0;                 // per-row float4 step (parked: 0)

        const float* xc = x + ((size_t)(b * CC + ch) << 16);
        const float4* fvp = g_fvp4 + (size_t)b * PLSZ4 +
                            (lv ? (h0 * SP4 + pq) : (ZROW * SP4));
        const float4* ivp = g_ivp4 + (size_t)b * PLSZ4 +
                            (lv ? ((h0 + 2) * SP4 + pq) : (ZROW * SP4));

        float4 pt[5], ps[5];
        float4 u = make_float4(0.f, 0.f, 0.f, 0.f);
        float4 v = make_float4(0.f, 0.f, 0.f, 0.f);

        // prologue: image rows h0-2..h0+1 -> ring slots 0..3
#pragma unroll
        for (int k = 0; k < 4; k++) {
            int r = h0 - 2 + k;
            int rc = r < 0 ? 0 : r;
            const float* xr = xc + (rc << 8);
            float2 xa = __ldg((const float2*)(xr + e0));
            float2 xb2 = __ldg((const float2*)(xr + e1));
            float4 fv = __ldg(fvp + k * f4s);
            float4 npt, nps;
            npt.x = xa.x * fabsf(fv.x);  nps.x = xa.x * fv.x;
            npt.y = xa.y * fabsf(fv.y);  nps.y = xa.y * fv.y;
            npt.z = xb2.x * fabsf(fv.z); nps.z = xb2.x * fv.z;
            npt.w = xb2.y * fabsf(fv.w); nps.w = xb2.y * fv.w;
            pt[k] = npt; ps[k] = nps;
            u.x += npt.x; u.y += npt.y; u.z += npt.z; u.w += npt.w;
            v.x += nps.x; v.y += nps.y; v.z += nps.z; v.w += nps.w;
        }
        pt[4] = make_float4(0.f, 0.f, 0.f, 0.f);
        ps[4] = make_float4(0.f, 0.f, 0.f, 0.f);
        fvp += 4 * f4s;

#pragma unroll 1
        for (int g6 = 0; g6 < 6; g6++) {
            const int rbase = h0 + 2 + g6 * 5;
#pragma unroll
            for (int k = 0; k < 5; k++) {
                const int sn = (k + 4) % 5;    // departing slot
                const int sc = (k + 2) % 5;    // center-row slot
                int r = rbase + k;
                int rc = r > 255 ? 255 : r;
                const float* xr = xc + (rc << 8);
                float2 xa = __ldg((const float2*)(xr + e0));
                float2 xb2 = __ldg((const float2*)(xr + e1));
                float4 fv = __ldg(fvp + k * f4s);
                float4 iv = __ldg(ivp + k * f4s);
                u.x -= pt[sn].x; u.y -= pt[sn].y; u.z -= pt[sn].z; u.w -= pt[sn].w;
                v.x -= ps[sn].x; v.y -= ps[sn].y; v.z -= ps[sn].z; v.w -= ps[sn].w;
                float4 npt, nps;
                npt.x = xa.x * fabsf(fv.x);  nps.x = xa.x * fv.x;
                npt.y = xa.y * fabsf(fv.y);  nps.y = xa.y * fv.y;
                npt.z = xb2.x * fabsf(fv.z); nps.z = xb2.x * fv.z;
                npt.w = xb2.y * fabsf(fv.w); nps.w = xb2.y * fv.w;
                pt[sn] = npt; ps[sn] = nps;
                u.x += npt.x; u.y += npt.y; u.z += npt.z; u.w += npt.w;
                v.x += nps.x; v.y += nps.y; v.z += nps.z; v.w += nps.w;
                // horizontal halo: 8 shuffles serve 4 output cols
                float ulz = __shfl_up_sync(FULLMASK, u.z, 1);
                float ulw = __shfl_up_sync(FULLMASK, u.w, 1);
                float urx = __shfl_down_sync(FULLMASK, u.x, 1);
                float ury = __shfl_down_sync(FULLMASK, u.y, 1);
                float vlz = __shfl_up_sync(FULLMASK, v.z, 1);
                float vlw = __shfl_up_sync(FULLMASK, v.w, 1);
                float vrx = __shfl_down_sync(FULLMASK, v.x, 1);
                float vry = __shfl_down_sync(FULLMASK, v.y, 1);
                // 5-wide window sums via running prefix
                float U0 = ulz + ulw + u.x + u.y + u.z;
                float U1 = U0 - ulz + u.w;
                float U2 = U1 - ulw + urx;
                float U3 = U2 - u.x + ury;
                float V0 = vlz + vlw + v.x + v.y + v.z;
                float V1 = V0 - vlz + v.w;
                float V2 = V1 - vlw + vrx;
                float V3 = V2 - v.x + vry;
                // epilogue: class = sign(iv); iv==0 -> no contribution
                float s0 = iv.x * mA, s1 = iv.y * mA;
                float s2 = iv.z * mB, s3 = iv.w * mB;
                float4 cen = pt[sc];           // = x at masked px (|f|=1)
                {
                    float a = fabsf(s0);
                    float tt = fmaf(0.5f, U0, -cen.x);
                    float dd = fmaf(-0.5f * s0, V0, fmaf(-tt, a, cen.x));
                    float q = dd * dd;
                    if (s0 > 0.f) acc1 += q; else if (s0 < 0.f) acc0 += q;
                }
                {
                    float a = fabsf(s1);
                    float tt = fmaf(0.5f, U1, -cen.y);
                    float dd = fmaf(-0.5f * s1, V1, fmaf(-tt, a, cen.y));
                    float q = dd * dd;
                    if (s1 > 0.f) acc1 += q; else if (s1 < 0.f) acc0 += q;
                }
                {
                    float a = fabsf(s2);
                    float tt = fmaf(0.5f, U2, -cen.z);
                    float dd = fmaf(-0.5f * s2, V2, fmaf(-tt, a, cen.z));
                    float q = dd * dd;
                    if (s2 > 0.f) acc1 += q; else if (s2 < 0.f) acc0 += q;
                }
                {
                    float a = fabsf(s3);
                    float tt = fmaf(0.5f, U3, -cen.w);
                    float dd = fmaf(-0.5f * s3, V3, fmaf(-tt, a, cen.w));
                    float q = dd * dd;
                    if (s3 > 0.f) acc1 += q; else if (s3 < 0.f) acc0 += q;
                }
            }
            fvp += 5 * f4s;
            ivp += 5 * f4s;
        }
    }

    // block reduction -> 2 double atomics per block
#pragma unroll
    for (int o = 16; o; o >>= 1) {
        acc0 += __shfl_xor_sync(FULLMASK, acc0, o);
        acc1 += __shfl_xor_sync(FULLMASK, acc1, o);
    }
    if (lane == 0) { sred[0][wid] = (double)acc0; sred[1][wid] = (double)acc1; }
    __syncthreads();
    if (threadIdx.x == 0) {
        double t0 = 0.0, t1 = 0.0;
#pragma unroll
        for (int i = 0; i < 8; i++) { t0 += sred[0][i]; t1 += sred[1][i]; }
        atomicAdd(&g_loss[0], t0);
        atomicAdd(&g_loss[1], t1);
    }
    gridsync();

    // ===== Phase 3: finalize ================================================
    if (blockIdx.x == 0 && threadIdx.x == 0) {
        double total = 0.0;
        int ncls = 0;
#pragma unroll
        for (int c = 0; c < 2; c++) {
            int ns = *(volatile int*)&g_nsel[c];
            int ca = *(volatile int*)&g_cal[c];
            double ls = *(volatile double*)&g_loss[c];
            bool valid = (ca >= 1) && (ns >= 1);
            double denom = (double)ns * 256.0;
            if (denom < 1.0) denom = 1.0;
            if (valid) { total += ls / denom; ncls++; }
        }
        out[0] = (ncls == 0) ? 0.0f : (float)(total / (double)ncls);
    }
}

extern "C" void kernel_launch(void* const* d_in, const int* in_sizes, int n_in,
                              void* d_out, int out_size) {
    const float* xfeat = (const float*)d_in[0];   // [4,256,256,256] f32
    const float* clf   = (const float*)d_in[1];   // [4,2,256,256]   f32
    const int*   gt    = (const int*)d_in[2];     // [4,256,256]     i32
    float* out = (float*)d_out;

    kernFused<<<NBLK, NTHR>>>(xfeat, clf, gt, out);
}

// round 9
// speedup vs baseline: 1.1349x; 1.1349x over previous
#include <cuda_runtime.h>

#define BB 4
#define CC 256
#define HH 256
#define WW 256
#define HWSZ (HH * WW)
#define NPIX (BB * HWSZ)
#define FULLMASK 0xFFFFFFFFu

#define NBLK 444
#define NTHR 256
#define NTH_TOT (NBLK * NTHR)          // 113664 threads
#define NWARP (NBLK * 8)               // 3552 warps
#define NTASK (3 * 9 * 4 * 256)        // 27648 warp-tasks
#define PROWS 274                      // 2 zero rows, 256 data, 16 zero rows
#define SP 272                         // plane row stride in floats (68 float4)
#define SP4 68
#define PLSZ (PROWS * SP)              // floats per (plane, b)
#define PLSZ4 (PLSZ / 4)               // 18632 float4
#define ZROW 258                       // guaranteed-zero plane row

// channel-independent planes (float4-aligned). Plane col = image col + 4.
// fv: +-1 if correct (sign = class) else 0.  iv: +-1/(cnt+1e-5) if mse-masked else 0.
__device__ float4 g_fvp4[BB * PLSZ4];
__device__ float4 g_ivp4[BB * PLSZ4];
__device__ unsigned char g_info[NPIX];
__device__ double g_loss[2];
__device__ int g_nsel[2], g_cal[2];
__device__ int g_bar_count = 0;
__device__ volatile int g_bar_gen = 0;

__device__ __forceinline__ void gridsync() {
    __syncthreads();
    if (threadIdx.x == 0) {
        __threadfence();
        int gen = g_bar_gen;
        if (atomicAdd(&g_bar_count, 1) == NBLK - 1) {
            g_bar_count = 0;
            __threadfence();
            g_bar_gen = gen + 1;
        } else {
            while (g_bar_gen == gen) { __nanosleep(64); }
        }
        __threadfence();
    }
    __syncthreads();
}

__global__ void __launch_bounds__(NTHR, 3) kernFused(
    const float* __restrict__ x, const float* __restrict__ clf,
    const int* __restrict__ gt, float* __restrict__ out) {
    __shared__ double sred[2][8];
    const int tid0 = blockIdx.x * NTHR + threadIdx.x;

    // ===== Phase 1a: zero planes + per-pixel info ==========================
    {
        const float4 z4 = make_float4(0.f, 0.f, 0.f, 0.f);
        for (int i = tid0; i < BB * PLSZ4; i += NTH_TOT) {
            g_fvp4[i] = z4;
            g_ivp4[i] = z4;
        }
    }
    for (int p = tid0; p < NPIX; p += NTH_TOT) {
        if (p == 0) {
            g_loss[0] = 0.0; g_loss[1] = 0.0;
            g_nsel[0] = 0; g_nsel[1] = 0;
            g_cal[0] = 0; g_cal[1] = 0;
        }
        int b = p >> 16;
        int hw = p & (HWSZ - 1);
        int h = hw >> 8;
        int w = hw & (WW - 1);
        int g = gt[p];
        float c0 = clf[(size_t)(b * 2) * HWSZ + hw];
        float c1 = clf[(size_t)(b * 2 + 1) * HWSZ + hw];
        int pred = (c1 > c0) ? 1 : 0;          // argmax ties -> index 0
        int correct = (pred == g) ? 1 : 0;
        int edge = (g == -1) ? 1 : 0;
        if (h < HH - 5) edge |= (gt[p + 5 * WW] != g) ? 1 : 0;
        if (w < WW - 5) edge |= (gt[p + 5] != g) ? 1 : 0;
        g_info[p] = (unsigned char)((g & 1) | (correct << 1) | (edge << 2));
    }
    gridsync();

    // ===== Phase 1b: ring counts -> fv/iv planes + counters =================
    for (int p = tid0; p < NPIX; p += NTH_TOT) {
        int b = p >> 16;
        int hw = p & (HWSZ - 1);
        int h = hw >> 8;
        int w = hw & (WW - 1);
        unsigned info = g_info[p];
        int g = info & 1;
        int correct = (info >> 1) & 1;
        int edge = (info >> 2) & 1;
        int cntCorr = 0, cntCls = 0;
#pragma unroll
        for (int dh = -2; dh <= 2; dh++) {
#pragma unroll
            for (int dw = -2; dw <= 2; dw++) {
                if (dh == 0 && dw == 0) continue;
                int hh = h + dh, wp = w + dw;
                if ((unsigned)hh < HH && (unsigned)wp < WW) {
                    unsigned qi = g_info[p + dh * WW + dw];
                    int same = ((int)(qi & 1) == g) ? 1 : 0;
                    cntCls += same;
                    cntCorr += same & (int)((qi >> 1) & 1);
                }
            }
        }
        int mse = correct & edge & (cntCorr >= 1 ? 1 : 0);
        int cal = edge & (cntCls >= 1 ? 1 : 0);

        float fv = correct ? (g ? 1.0f : -1.0f) : 0.0f;
        float inv = 1.0f / ((float)cntCorr + 1e-5f);
        float ivs = mse ? (g ? inv : -inv) : 0.0f;

        int pofs = (h + 2) * SP + (w + 4);
        ((float*)g_fvp4)[(size_t)b * PLSZ + pofs] = fv;
        ((float*)g_ivp4)[(size_t)b * PLSZ + pofs] = ivs;

        unsigned bm;
        bm = __ballot_sync(FULLMASK, mse && g == 0);
        if ((threadIdx.x & 31) == 0 && bm) atomicAdd(&g_nsel[0], __popc(bm));
        bm = __ballot_sync(FULLMASK, mse && g == 1);
        if ((threadIdx.x & 31) == 0 && bm) atomicAdd(&g_nsel[1], __popc(bm));
        bm = __ballot_sync(FULLMASK, cal && g == 0);
        if ((threadIdx.x & 31) == 0 && bm) atomicAdd(&g_cal[0], __popc(bm));
        bm = __ballot_sync(FULLMASK, cal && g == 1);
        if ((threadIdx.x & 31) == 0 && bm) atomicAdd(&g_cal[1], __popc(bm));
    }
    gridsync();

    // ===== Phase 2: separable 2-class box filter, 4 aligned cols/lane =======
    // Task = (wband, hband, b, ch): 30 output rows x 120 output cols.
    // Lane owns image cols cb..cb+3, cb = 120*wb - 4 + 4*lane (ALWAYS float4-
    // aligned). Lanes 1..30 output; lanes 0/31 provide halo column sums only.
    // Vertical: 5-slot ring of pt = x*|fv|, ps = x*fv; running sums u,v.
    // Horizontal: 8 shuffles/row serve 120 px. All boundaries data-driven:
    // zero-padded planes, clamped x addresses, stride-0 parked pointers.
    const int lane = threadIdx.x & 31;
    const int wid = threadIdx.x >> 5;
    const int gwarp = blockIdx.x * 8 + wid;
    float acc0 = 0.f, acc1 = 0.f;

#pragma unroll 1
    for (int t = gwarp; t < NTASK; t += NWARP) {
        int wb = t % 3;
        int r1 = t / 3;
        int hb = r1 % 9;
        int r2 = r1 / 9;
        int b = r2 & 3;
        int ch = r2 >> 2;
        int h0 = hb * 30;
        int cb = wb * 120 - 4 + (lane << 2);   // aligned: cb % 4 == 0
        bool lv = (cb <= 264);                 // plane cols cb+4..cb+7 <= 271
        bool qv = lv && (lane >= 1) && (lane <= 30);
        int xoff = min(max(cb, 0), 252);
        int pq = (cb + 4) >> 2;                // float4 col in planes

        const float* xc = x + ((size_t)(b * CC + ch) << 16) + xoff;
        const float4* plb = g_fvp4 + (size_t)b * PLSZ4;
        const float4* ilb = g_ivp4 + (size_t)b * PLSZ4;
        const float4* fvp = lv ? (plb + h0 * SP4 + pq) : (plb + ZROW * SP4);
        const float4* ivp = qv ? (ilb + (h0 + 2) * SP4 + pq) : (ilb + ZROW * SP4);
        const int fstep = lv ? SP4 : 0;
        const int istep = qv ? SP4 : 0;

        float4 pt[5], ps[5];
        float4 u = make_float4(0.f, 0.f, 0.f, 0.f);
        float4 v = make_float4(0.f, 0.f, 0.f, 0.f);

        // prologue: image rows h0-2..h0+1 -> ring slots 0..3
#pragma unroll
        for (int k = 0; k < 4; k++) {
            int r = h0 - 2 + k;
            int rc = r < 0 ? 0 : r;
            float4 xv = __ldg((const float4*)(xc + (rc << 8)));
            float4 fv = __ldg(fvp);
            fvp += fstep;
            float4 npt, nps;
            npt.x = xv.x * fabsf(fv.x); nps.x = xv.x * fv.x;
            npt.y = xv.y * fabsf(fv.y); nps.y = xv.y * fv.y;
            npt.z = xv.z * fabsf(fv.z); nps.z = xv.z * fv.z;
            npt.w = xv.w * fabsf(fv.w); nps.w = xv.w * fv.w;
            pt[k] = npt; ps[k] = nps;
            u.x += npt.x; u.y += npt.y; u.z += npt.z; u.w += npt.w;
            v.x += nps.x; v.y += nps.y; v.z += nps.z; v.w += nps.w;
        }
        pt[4] = make_float4(0.f, 0.f, 0.f, 0.f);
        ps[4] = make_float4(0.f, 0.f, 0.f, 0.f);

#pragma unroll 1
        for (int g6 = 0; g6 < 6; g6++) {
            const int rbase = h0 + 2 + g6 * 5;
#pragma unroll
            for (int k = 0; k < 5; k++) {
                const int sn = (k + 4) % 5;    // departing slot
                const int sc = (k + 2) % 5;    // center-row slot
                int r = rbase + k;
                int rc = r > 255 ? 255 : r;
                float4 xv = __ldg((const float4*)(xc + (rc << 8)));
                float4 fv = __ldg(fvp);
                float4 iv = __ldg(ivp);
                fvp += fstep;
                ivp += istep;
                u.x -= pt[sn].x; u.y -= pt[sn].y; u.z -= pt[sn].z; u.w -= pt[sn].w;
                v.x -= ps[sn].x; v.y -= ps[sn].y; v.z -= ps[sn].z; v.w -= ps[sn].w;
                float4 npt, nps;
                npt.x = xv.x * fabsf(fv.x); nps.x = xv.x * fv.x;
                npt.y = xv.y * fabsf(fv.y); nps.y = xv.y * fv.y;
                npt.z = xv.z * fabsf(fv.z); nps.z = xv.z * fv.z;
                npt.w = xv.w * fabsf(fv.w); nps.w = xv.w * fv.w;
                pt[sn] = npt; ps[sn] = nps;
                u.x += npt.x; u.y += npt.y; u.z += npt.z; u.w += npt.w;
                v.x += nps.x; v.y += nps.y; v.z += nps.z; v.w += nps.w;
                // horizontal halo: 8 shuffles serve 4 output cols
                float ulz = __shfl_up_sync(FULLMASK, u.z, 1);
                float ulw = __shfl_up_sync(FULLMASK, u.w, 1);
                float urx = __shfl_down_sync(FULLMASK, u.x, 1);
                float ury = __shfl_down_sync(FULLMASK, u.y, 1);
                float vlz = __shfl_up_sync(FULLMASK, v.z, 1);
                float vlw = __shfl_up_sync(FULLMASK, v.w, 1);
                float vrx = __shfl_down_sync(FULLMASK, v.x, 1);
                float vry = __shfl_down_sync(FULLMASK, v.y, 1);
                // 5-wide window sums via running prefix
                float U0 = ulz + ulw + u.x + u.y + u.z;
                float U1 = U0 - ulz + u.w;
                float U2 = U1 - ulw + urx;
                float U3 = U2 - u.x + ury;
                float V0 = vlz + vlw + v.x + v.y + v.z;
                float V1 = V0 - vlz + v.w;
                float V2 = V1 - vlw + vrx;
                float V3 = V2 - v.x + vry;
                // epilogue: class = sign(iv); iv==0 -> no contribution
                float4 cen = pt[sc];           // = x at masked px (|fv|=1)
                {
                    float s = iv.x, a = fabsf(s);
                    float tt = fmaf(0.5f, U0, -cen.x);
                    float dd = fmaf(-0.5f * s, V0, fmaf(-tt, a, cen.x));
                    float q = dd * dd;
                    if (s > 0.f) acc1 += q; else if (s < 0.f) acc0 += q;
                }
                {
                    float s = iv.y, a = fabsf(s);
                    float tt = fmaf(0.5f, U1, -cen.y);
                    float dd = fmaf(-0.5f * s, V1, fmaf(-tt, a, cen.y));
                    float q = dd * dd;
                    if (s > 0.f) acc1 += q; else if (s < 0.f) acc0 += q;
                }
                {
                    float s = iv.z, a = fabsf(s);
                    float tt = fmaf(0.5f, U2, -cen.z);
                    float dd = fmaf(-0.5f * s, V2, fmaf(-tt, a, cen.z));
                    float q = dd * dd;
                    if (s > 0.f) acc1 += q; else if (s < 0.f) acc0 += q;
                }
                {
                    float s = iv.w, a = fabsf(s);
                    float tt = fmaf(0.5f, U3, -cen.w);
                    float dd = fmaf(-0.5f * s, V3, fmaf(-tt, a, cen.w));
                    float q = dd * dd;
                    if (s > 0.f) acc1 += q; else if (s < 0.f) acc0 += q;
                }
            }
        }
    }

    // block reduction -> 2 double atomics per block
#pragma unroll
    for (int o = 16; o; o >>= 1) {
        acc0 += __shfl_xor_sync(FULLMASK, acc0, o);
        acc1 += __shfl_xor_sync(FULLMASK, acc1, o);
    }
    if (lane == 0) { sred[0][wid] = (double)acc0; sred[1][wid] = (double)acc1; }
    __syncthreads();
    if (threadIdx.x == 0) {
        double t0 = 0.0, t1 = 0.0;
#pragma unroll
        for (int i = 0; i < 8; i++) { t0 += sred[0][i]; t1 += sred[1][i]; }
        atomicAdd(&g_loss[0], t0);
        atomicAdd(&g_loss[1], t1);
    }
    gridsync();

    // ===== Phase 3: finalize ================================================
    if (blockIdx.x == 0 && threadIdx.x == 0) {
        double total = 0.0;
        int ncls = 0;
#pragma unroll
        for (int c = 0; c < 2; c++) {
            int ns = *(volatile int*)&g_nsel[c];
            int ca = *(volatile int*)&g_cal[c];
            double ls = *(volatile double*)&g_loss[c];
            bool valid = (ca >= 1) && (ns >= 1);
            double denom = (double)ns * 256.0;
            if (denom < 1.0) denom = 1.0;
            if (valid) { total += ls / denom; ncls++; }
        }
        out[0] = (ncls == 0) ? 0.0f : (float)(total / (double)ncls);
    }
}

extern "C" void kernel_launch(void* const* d_in, const int* in_sizes, int n_in,
                              void* d_out, int out_size) {
    const float* xfeat = (const float*)d_in[0];   // [4,256,256,256] f32
    const float* clf   = (const float*)d_in[1];   // [4,2,256,256]   f32
    const int*   gt    = (const int*)d_in[2];     // [4,256,256]     i32
    float* out = (float*)d_out;

    kernFused<<<NBLK, NTHR>>>(xfeat, clf, gt, out);
}

// round 11
// speedup vs baseline: 1.5087x; 1.3293x over previous
#include <cuda_runtime.h>

#define BB 4
#define CC 256
#define HH 256
#define WW 256
#define HWSZ (HH * WW)
#define NPIX (BB * HWSZ)
#define FULLMASK 0xFFFFFFFFu

// plane geometry: row stride 272 floats (68 float4), plane col = image col + 4
// rows: 0,1 zero | 2..257 data (image rows 0..255) | 258..295 zero
#define SP 272
#define SP4 68
#define PROWS 296
#define PLSZ (PROWS * SP)
#define PLSZ4 (PROWS * SP4)
#define PARKROW 262                    // parked lanes walk rows 262..295 (all zero)

// fv: +-1 if correct (sign = class) else 0.  iv: +-1/(cnt+1e-5) if mse-masked else 0.
__device__ float4 g_fvp4[BB * PLSZ4];
__device__ float4 g_ivp4[BB * PLSZ4];
__device__ unsigned char g_info[NPIX];
__device__ double g_loss[2];
__device__ int g_nsel[2], g_cal[2];

// ---------------- Kernel A: zero planes + per-pixel info -------------------
__global__ void kernA(const int* __restrict__ gt, const float* __restrict__ clf) {
    int p = blockIdx.x * blockDim.x + threadIdx.x;
    const float4 z4 = make_float4(0.f, 0.f, 0.f, 0.f);
    for (int i = p; i < BB * PLSZ4; i += NPIX) { g_fvp4[i] = z4; g_ivp4[i] = z4; }
    if (p == 0) {
        g_loss[0] = 0.0; g_loss[1] = 0.0;
        g_nsel[0] = 0; g_nsel[1] = 0;
        g_cal[0] = 0; g_cal[1] = 0;
    }
    int b = p >> 16;
    int hw = p & (HWSZ - 1);
    int h = hw >> 8;
    int w = hw & (WW - 1);
    int g = gt[p];
    float c0 = clf[(size_t)(b * 2) * HWSZ + hw];
    float c1 = clf[(size_t)(b * 2 + 1) * HWSZ + hw];
    int pred = (c1 > c0) ? 1 : 0;              // argmax ties -> index 0
    int correct = (pred == g) ? 1 : 0;
    int edge = (g == -1) ? 1 : 0;
    if (h < HH - 5) edge |= (gt[p + 5 * WW] != g) ? 1 : 0;
    if (w < WW - 5) edge |= (gt[p + 5] != g) ? 1 : 0;
    g_info[p] = (unsigned char)((g & 1) | (correct << 1) | (edge << 2));
}

// ---------------- Kernel B: ring counts -> fv/iv planes + counters ---------
__global__ void kernB() {
    int p = blockIdx.x * blockDim.x + threadIdx.x;
    int hw = p & (HWSZ - 1);
    int h = hw >> 8;
    int w = hw & (WW - 1);
    int b = p >> 16;
    unsigned info = g_info[p];
    int g = info & 1;
    int correct = (info >> 1) & 1;
    int edge = (info >> 2) & 1;
    int cntCorr = 0, cntCls = 0;
#pragma unroll
    for (int dh = -2; dh <= 2; dh++) {
#pragma unroll
        for (int dw = -2; dw <= 2; dw++) {
            if (dh == 0 && dw == 0) continue;
            int hh = h + dh, wp = w + dw;
            if ((unsigned)hh < HH && (unsigned)wp < WW) {
                unsigned qi = g_info[p + dh * WW + dw];
                int same = ((int)(qi & 1) == g) ? 1 : 0;
                cntCls += same;
                cntCorr += same & (int)((qi >> 1) & 1);
            }
        }
    }
    int mse = correct & edge & (cntCorr >= 1 ? 1 : 0);
    int cal = edge & (cntCls >= 1 ? 1 : 0);

    float fv = correct ? (g ? 1.0f : -1.0f) : 0.0f;
    float inv = 1.0f / ((float)cntCorr + 1e-5f);
    float ivs = mse ? (g ? inv : -inv) : 0.0f;

    int pofs = (h + 2) * SP + (w + 4);
    ((float*)g_fvp4)[(size_t)b * PLSZ + pofs] = fv;
    ((float*)g_ivp4)[(size_t)b * PLSZ + pofs] = ivs;

    unsigned bm;
    bm = __ballot_sync(FULLMASK, mse && g == 0);
    if ((threadIdx.x & 31) == 0 && bm) atomicAdd(&g_nsel[0], __popc(bm));
    bm = __ballot_sync(FULLMASK, mse && g == 1);
    if ((threadIdx.x & 31) == 0 && bm) atomicAdd(&g_nsel[1], __popc(bm));
    bm = __ballot_sync(FULLMASK, cal && g == 0);
    if ((threadIdx.x & 31) == 0 && bm) atomicAdd(&g_cal[0], __popc(bm));
    bm = __ballot_sync(FULLMASK, cal && g == 1);
    if ((threadIdx.x & 31) == 0 && bm) atomicAdd(&g_cal[1], __popc(bm));
}

// ---------------- Kernel C: ringless 2-channel separable box filter --------
// Task = (wband 3, hband 9, b 4, chpair 128): 30 output rows x 120 cols x 2 ch.
// Lane owns image cols cb..cb+3, cb = 120*wb - 4 + 4*lane (float4-aligned).
// NO register ring: departing products recomputed from L1-hot reloads of
// x(r-2), fv(r-2). Channel 2 accessed purely via +HWSZ immediate offsets.
// Plane row = image row + 2: incoming r+2 -> plane k+4; center/iv r -> plane
// k+2; departing r-2 -> plane k (prologue image h0-2+j -> plane h0+j).
#define NTASK (3 * 9 * 4 * 128)        // 13824 warp-tasks
#define NBLKC (NTASK / 8)              // 1728 blocks

__global__ void __launch_bounds__(256, 4) kernC(const float* __restrict__ x) {
    __shared__ double sred[2][8];
    const int lane = threadIdx.x & 31;
    const int wid = threadIdx.x >> 5;
    const int t = blockIdx.x * 8 + wid;

    const int wb = t % 3;
    const int r1 = t / 3;
    const int hb = r1 % 9;
    const int r2 = r1 / 9;
    const int b = r2 & 3;
    const int ch = (r2 >> 2) << 1;     // channel pair
    const int h0 = hb * 30;
    const int cb = wb * 120 - 4 + (lane << 2);
    const bool lv = (cb <= 264);
    const bool qv = lv && (lane >= 1) && (lane <= 30);
    const int xoff = min(max(cb, 0), 252);
    const int pq = (cb + 4) >> 2;

    const float* xp = x + ((size_t)(b * CC + ch) << 16) + xoff;
    const float4* pf = g_fvp4 + (size_t)b * PLSZ4 +
                       (lv ? (h0 * SP4 + pq) : (PARKROW * SP4));
    const float4* pi = g_ivp4 + (size_t)b * PLSZ4 +
                       (qv ? (h0 * SP4 + pq) : (PARKROW * SP4));

    float4 u1 = make_float4(0.f, 0.f, 0.f, 0.f), v1 = u1, u2 = u1, v2 = u1;

    // prologue: fold image rows h0-2..h0+1 (plane rows h0..h0+3) into u,v
#pragma unroll
    for (int j = 0; j < 4; j++) {
        int rr = h0 - 2 + j;
        int rc = rr < 0 ? 0 : rr;
        const float* xr = xp + (rc << 8);
        float4 xa = __ldg((const float4*)xr);
        float4 xb2 = __ldg((const float4*)(xr + HWSZ));
        float4 f = __ldg(pf + j * SP4);
        float4 s, w_;
        s.x = xa.x * f.x; s.y = xa.y * f.y; s.z = xa.z * f.z; s.w = xa.w * f.w;
        w_.x = s.x * f.x; w_.y = s.y * f.y; w_.z = s.z * f.z; w_.w = s.w * f.w;
        u1.x += w_.x; u1.y += w_.y; u1.z += w_.z; u1.w += w_.w;
        v1.x += s.x;  v1.y += s.y;  v1.z += s.z;  v1.w += s.w;
        s.x = xb2.x * f.x; s.y = xb2.y * f.y; s.z = xb2.z * f.z; s.w = xb2.w * f.w;
        w_.x = s.x * f.x; w_.y = s.y * f.y; w_.z = s.z * f.z; w_.w = s.w * f.w;
        u2.x += w_.x; u2.y += w_.y; u2.z += w_.z; u2.w += w_.w;
        v2.x += s.x;  v2.y += s.y;  v2.z += s.z;  v2.w += s.w;
    }

    float acc0 = 0.f, acc1 = 0.f;

#pragma unroll 1
    for (int g6 = 0; g6 < 6; g6++) {
        const int rb = h0 + g6 * 5;
        const float4* pfg = pf + g6 * 5 * SP4;
        const float4* pig = pi + g6 * 5 * SP4;
#pragma unroll
        for (int k = 0; k < 5; k++) {
            const int r = rb + k;
            const int ri = min(r + 2, 255);
            const int rd = min(max(r - 2, 0), 255);
            const int rcn = min(r, 255);
            const float* xi = xp + (ri << 8);
            const float* xd = xp + (rd << 8);
            const float* xcn = xp + (rcn << 8);
            float4 fin = __ldg(pfg + (k + 4) * SP4);   // fv at image row r+2
            float4 fdp = __ldg(pfg + k * SP4);         // fv at image row r-2
            float4 iv  = __ldg(pig + (k + 2) * SP4);   // iv at image row r
            float4 x1i = __ldg((const float4*)xi);
            float4 x2i = __ldg((const float4*)(xi + HWSZ));
            float4 x1d = __ldg((const float4*)xd);
            float4 x2d = __ldg((const float4*)(xd + HWSZ));
            float4 x1c = __ldg((const float4*)xcn);
            float4 x2c = __ldg((const float4*)(xcn + HWSZ));

            // incoming products (pt = ps*fv since fv^2 = |fv|)
            {
                float4 s, w_;
                s.x = x1i.x * fin.x; s.y = x1i.y * fin.y; s.z = x1i.z * fin.z; s.w = x1i.w * fin.w;
                w_.x = s.x * fin.x; w_.y = s.y * fin.y; w_.z = s.z * fin.z; w_.w = s.w * fin.w;
                u1.x += w_.x; u1.y += w_.y; u1.z += w_.z; u1.w += w_.w;
                v1.x += s.x;  v1.y += s.y;  v1.z += s.z;  v1.w += s.w;
                s.x = x2i.x * fin.x; s.y = x2i.y * fin.y; s.z = x2i.z * fin.z; s.w = x2i.w * fin.w;
                w_.x = s.x * fin.x; w_.y = s.y * fin.y; w_.z = s.z * fin.z; w_.w = s.w * fin.w;
                u2.x += w_.x; u2.y += w_.y; u2.z += w_.z; u2.w += w_.w;
                v2.x += s.x;  v2.y += s.y;  v2.z += s.z;  v2.w += s.w;
            }

            // ---- channel 1: shuffles, windows, epilogue ----
            {
                float ulz = __shfl_up_sync(FULLMASK, u1.z, 1);
                float ulw = __shfl_up_sync(FULLMASK, u1.w, 1);
                float urx = __shfl_down_sync(FULLMASK, u1.x, 1);
                float ury = __shfl_down_sync(FULLMASK, u1.y, 1);
                float vlz = __shfl_up_sync(FULLMASK, v1.z, 1);
                float vlw = __shfl_up_sync(FULLMASK, v1.w, 1);
                float vrx = __shfl_down_sync(FULLMASK, v1.x, 1);
                float vry = __shfl_down_sync(FULLMASK, v1.y, 1);
                float U0 = ulz + ulw + u1.x + u1.y + u1.z;
                float U1 = U0 - ulz + u1.w;
                float U2 = U1 - ulw + urx;
                float U3 = U2 - u1.x + ury;
                float V0 = vlz + vlw + v1.x + v1.y + v1.z;
                float V1 = V0 - vlz + v1.w;
                float V2 = V1 - vlw + vrx;
                float V3 = V2 - v1.x + vry;
                {
                    float s = iv.x, a = fabsf(s);
                    float tt = fmaf(0.5f, U0, -x1c.x);
                    float dd = fmaf(-0.5f * s, V0, fmaf(-tt, a, x1c.x));
                    float q = dd * dd;
                    if (s > 0.f) acc1 += q; else if (s < 0.f) acc0 += q;
                }
                {
                    float s = iv.y, a = fabsf(s);
                    float tt = fmaf(0.5f, U1, -x1c.y);
                    float dd = fmaf(-0.5f * s, V1, fmaf(-tt, a, x1c.y));
                    float q = dd * dd;
                    if (s > 0.f) acc1 += q; else if (s < 0.f) acc0 += q;
                }
                {
                    float s = iv.z, a = fabsf(s);
                    float tt = fmaf(0.5f, U2, -x1c.z);
                    float dd = fmaf(-0.5f * s, V2, fmaf(-tt, a, x1c.z));
                    float q = dd * dd;
                    if (s > 0.f) acc1 += q; else if (s < 0.f) acc0 += q;
                }
                {
                    float s = iv.w, a = fabsf(s);
                    float tt = fmaf(0.5f, U3, -x1c.w);
                    float dd = fmaf(-0.5f * s, V3, fmaf(-tt, a, x1c.w));
                    float q = dd * dd;
                    if (s > 0.f) acc1 += q; else if (s < 0.f) acc0 += q;
                }
            }

            // ---- channel 2: shuffles, windows, epilogue ----
            {
                float ulz = __shfl_up_sync(FULLMASK, u2.z, 1);
                float ulw = __shfl_up_sync(FULLMASK, u2.w, 1);
                float urx = __shfl_down_sync(FULLMASK, u2.x, 1);
                float ury = __shfl_down_sync(FULLMASK, u2.y, 1);
                float vlz = __shfl_up_sync(FULLMASK, v2.z, 1);
                float vlw = __shfl_up_sync(FULLMASK, v2.w, 1);
                float vrx = __shfl_down_sync(FULLMASK, v2.x, 1);
                float vry = __shfl_down_sync(FULLMASK, v2.y, 1);
                float U0 = ulz + ulw + u2.x + u2.y + u2.z;
                float U1 = U0 - ulz + u2.w;
                float U2 = U1 - ulw + urx;
                float U3 = U2 - u2.x + ury;
                float V0 = vlz + vlw + v2.x + v2.y + v2.z;
                float V1 = V0 - vlz + v2.w;
                float V2 = V1 - vlw + vrx;
                float V3 = V2 - v2.x + vry;
                {
                    float s = iv.x, a = fabsf(s);
                    float tt = fmaf(0.5f, U0, -x2c.x);
                    float dd = fmaf(-0.5f * s, V0, fmaf(-tt, a, x2c.x));
                    float q = dd * dd;
                    if (s > 0.f) acc1 += q; else if (s < 0.f) acc0 += q;
                }
                {
                    float s = iv.y, a = fabsf(s);
                    float tt = fmaf(0.5f, U1, -x2c.y);
                    float dd = fmaf(-0.5f * s, V1, fmaf(-tt, a, x2c.y));
                    float q = dd * dd;
                    if (s > 0.f) acc1 += q; else if (s < 0.f) acc0 += q;
                }
                {
                    float s = iv.z, a = fabsf(s);
                    float tt = fmaf(0.5f, U2, -x2c.z);
                    float dd = fmaf(-0.5f * s, V2, fmaf(-tt, a, x2c.z));
                    float q = dd * dd;
                    if (s > 0.f) acc1 += q; else if (s < 0.f) acc0 += q;
                }
                {
                    float s = iv.w, a = fabsf(s);
                    float tt = fmaf(0.5f, U3, -x2c.w);
                    float dd = fmaf(-0.5f * s, V3, fmaf(-tt, a, x2c.w));
                    float q = dd * dd;
                    if (s > 0.f) acc1 += q; else if (s < 0.f) acc0 += q;
                }
            }

            // departing products (recomputed; L1-hot reloads)
            {
                float4 s, w_;
                s.x = x1d.x * fdp.x; s.y = x1d.y * fdp.y; s.z = x1d.z * fdp.z; s.w = x1d.w * fdp.w;
                w_.x = s.x * fdp.x; w_.y = s.y * fdp.y; w_.z = s.z * fdp.z; w_.w = s.w * fdp.w;
                u1.x -= w_.x; u1.y -= w_.y; u1.z -= w_.z; u1.w -= w_.w;
                v1.x -= s.x;  v1.y -= s.y;  v1.z -= s.z;  v1.w -= s.w;
                s.x = x2d.x * fdp.x; s.y = x2d.y * fdp.y; s.z = x2d.z * fdp.z; s.w = x2d.w * fdp.w;
                w_.x = s.x * fdp.x; w_.y = s.y * fdp.y; w_.z = s.z * fdp.z; w_.w = s.w * fdp.w;
                u2.x -= w_.x; u2.y -= w_.y; u2.z -= w_.z; u2.w -= w_.w;
                v2.x -= s.x;  v2.y -= s.y;  v2.z -= s.z;  v2.w -= s.w;
            }
        }
    }

    // block reduction -> 2 double atomics per block
#pragma unroll
    for (int o = 16; o; o >>= 1) {
        acc0 += __shfl_xor_sync(FULLMASK, acc0, o);
        acc1 += __shfl_xor_sync(FULLMASK, acc1, o);
    }
    if (lane == 0) { sred[0][wid] = (double)acc0; sred[1][wid] = (double)acc1; }
    __syncthreads();
    if (threadIdx.x == 0) {
        double t0 = 0.0, t1 = 0.0;
#pragma unroll
        for (int i = 0; i < 8; i++) { t0 += sred[0][i]; t1 += sred[1][i]; }
        atomicAdd(&g_loss[0], t0);
        atomicAdd(&g_loss[1], t1);
    }
}

// ---------------- Kernel D: finalize ---------------------------------------
__global__ void kernD(float* out) {
    double total = 0.0;
    int ncls = 0;
#pragma unroll
    for (int c = 0; c < 2; c++) {
        bool valid = (g_cal[c] >= 1) && (g_nsel[c] >= 1);
        double denom = (double)g_nsel[c] * 256.0;
        if (denom < 1.0) denom = 1.0;
        double lc = g_loss[c] / denom;
        if (valid) { total += lc; ncls++; }
    }
    out[0] = (ncls == 0) ? 0.0f : (float)(total / (double)ncls);
}

extern "C" void kernel_launch(void* const* d_in, const int* in_sizes, int n_in,
                              void* d_out, int out_size) {
    const float* xfeat = (const float*)d_in[0];   // [4,256,256,256] f32
    const float* clf   = (const float*)d_in[1];   // [4,2,256,256]   f32
    const int*   gt    = (const int*)d_in[2];     // [4,256,256]     i32
    float* out = (float*)d_out;

    kernA<<<NPIX / 256, 256>>>(gt, clf);
    kernB<<<NPIX / 256, 256>>>();
    kernC<<<NBLKC, 256>>>(xfeat);
    kernD<<<1, 1>>>(out);
}